// round 10
// baseline (speedup 1.0000x reference)
#include <cuda_runtime.h>
#include <cuda_bf16.h>
#include <cstdint>

#define BATCH  64
#define TSTEPS 1024
#define DDIM   512
#define FDIM   512
#define MTOT   (BATCH * TSTEPS)   // 65536

#define CLUSTER 8
#define NB      4
#define FCHUNK  64
#define NCLUST  (BATCH / NB)
#define NCTA2   (NCLUST * CLUSTER)

// ---------------------------------------------------------------------------
// Split-bf16 scratch (device globals: allowed scratch, no allocation)
// ---------------------------------------------------------------------------
__device__ __nv_bfloat16 g_Ahi[(size_t)MTOT * DDIM];   // 64 MB
__device__ __nv_bfloat16 g_Alo[(size_t)MTOT * DDIM];   // 64 MB
__device__ __nv_bfloat16 g_Whi[DDIM * FDIM];           // 512 KB
__device__ __nv_bfloat16 g_Wlo[DDIM * FDIM];           // 512 KB

__device__ __forceinline__ void split2_(float v, unsigned short& h, unsigned short& l) {
    __nv_bfloat16 hb = __float2bfloat16_rn(v);
    __nv_bfloat16 lb = __float2bfloat16_rn(v - __bfloat162float(hb));
    h = __bfloat16_as_ushort(hb);
    l = __bfloat16_as_ushort(lb);
}

// one thread handles 4 consecutive floats -> packed uint2 hi + uint2 lo
__global__ __launch_bounds__(256) void conv_A_kernel(const float* __restrict__ in) {
    size_t i = ((size_t)blockIdx.x * blockDim.x + threadIdx.x) * 4;
    float4 v = *(const float4*)(in + i);
    unsigned short h0, h1, h2, h3, l0, l1, l2, l3;
    split2_(v.x, h0, l0); split2_(v.y, h1, l1);
    split2_(v.z, h2, l2); split2_(v.w, h3, l3);
    uint2 ph = make_uint2((uint32_t)h0 | ((uint32_t)h1 << 16),
                          (uint32_t)h2 | ((uint32_t)h3 << 16));
    uint2 pl = make_uint2((uint32_t)l0 | ((uint32_t)l1 << 16),
                          (uint32_t)l2 | ((uint32_t)l3 << 16));
    *(uint2*)(g_Ahi + i) = ph;
    *(uint2*)(g_Alo + i) = pl;
}

__global__ __launch_bounds__(256) void conv_W_kernel(const float* __restrict__ in) {
    size_t i = ((size_t)blockIdx.x * blockDim.x + threadIdx.x) * 4;
    float4 v = *(const float4*)(in + i);
    unsigned short h0, h1, h2, h3, l0, l1, l2, l3;
    split2_(v.x, h0, l0); split2_(v.y, h1, l1);
    split2_(v.z, h2, l2); split2_(v.w, h3, l3);
    uint2 ph = make_uint2((uint32_t)h0 | ((uint32_t)h1 << 16),
                          (uint32_t)h2 | ((uint32_t)h3 << 16));
    uint2 pl = make_uint2((uint32_t)l0 | ((uint32_t)l1 << 16),
                          (uint32_t)l2 | ((uint32_t)l3 << 16));
    *(uint2*)(g_Whi + i) = ph;
    *(uint2*)(g_Wlo + i) = pl;
}

// ---------------------------------------------------------------------------
// Phase 1: x_proj = A @ W + bias via split-bf16 HMMA (3 products, fp32 acc)
// CTA tile 128x128, K-tile 64; 8 warps as 4(M) x 2(N), warp tile 32x64.
// ---------------------------------------------------------------------------
// smem bytes: Ahi[128][72]h, Alo, Bhi[64][136]h, Blo  (padded rows)
#define XA_STRIDE 72
#define XB_STRIDE 136
#define OFF_AHI 0
#define OFF_ALO 18432
#define OFF_BHI 36864
#define OFF_BLO 54272
#define XP_SMEM 71680

__device__ __forceinline__ void ldsm4_(uint32_t* r, uint32_t addr) {
    asm volatile("ldmatrix.sync.aligned.m8n8.x4.shared.b16 {%0,%1,%2,%3}, [%4];"
                 : "=r"(r[0]), "=r"(r[1]), "=r"(r[2]), "=r"(r[3]) : "r"(addr));
}
__device__ __forceinline__ void ldsm4t_(uint32_t* r, uint32_t addr) {
    asm volatile("ldmatrix.sync.aligned.m8n8.x4.trans.shared.b16 {%0,%1,%2,%3}, [%4];"
                 : "=r"(r[0]), "=r"(r[1]), "=r"(r[2]), "=r"(r[3]) : "r"(addr));
}
__device__ __forceinline__ void mma16816_(float* d, const uint32_t* a,
                                          uint32_t b0, uint32_t b1) {
    asm volatile(
        "mma.sync.aligned.m16n8k16.row.col.f32.bf16.bf16.f32 "
        "{%0,%1,%2,%3}, {%4,%5,%6,%7}, {%8,%9}, {%0,%1,%2,%3};"
        : "+f"(d[0]), "+f"(d[1]), "+f"(d[2]), "+f"(d[3])
        : "r"(a[0]), "r"(a[1]), "r"(a[2]), "r"(a[3]), "r"(b0), "r"(b1));
}

extern __shared__ char xsmem[];

__global__ __launch_bounds__(256, 2) void xproj_mma_kernel(
    const float* __restrict__ bias,  // [512]
    float* __restrict__ C)           // [65536, 512]
{
    const int tid  = threadIdx.x;
    const int lane = tid & 31;
    const int wid  = tid >> 5;
    const int m0 = blockIdx.y * 128;
    const int n0 = blockIdx.x * 128;
    const int m_w = (wid >> 1) * 32;   // warp M offset in tile
    const int n_w = (wid & 1) * 64;    // warp N offset in tile

    uint32_t sm;
    asm("{ .reg .u64 t; cvta.to.shared.u64 t, %1; cvt.u32.u64 %0, t; }"
        : "=r"(sm) : "l"(xsmem));

    // ldmatrix lane addressing (canonical m16n8k16 mapping)
    const int a_row   = (lane & 15);          // within m16
    const int a_khalf = (lane >> 4) & 1;      // k 8-half group
    const int b_krow  = (lane & 7) + (((lane >> 3) & 1) << 3);  // within k16
    const int b_ncol8 = ((lane >> 4) & 1) << 3;                 // n 8-col group

    // per-mt A byte bases (kc adds kc*32 bytes)
    uint32_t aHiB[2], aLoB[2];
#pragma unroll
    for (int mt = 0; mt < 2; mt++) {
        const uint32_t rb =
            (uint32_t)(((m_w + mt * 16 + a_row) * XA_STRIDE + a_khalf * 8) * 2);
        aHiB[mt] = sm + OFF_AHI + rb;
        aLoB[mt] = sm + OFF_ALO + rb;
    }
    // B byte base (kc adds kc*16*XB_STRIDE*2, nt16 adds nt16*32)
    const uint32_t bRel =
        (uint32_t)((b_krow * XB_STRIDE + n_w + b_ncol8) * 2);
    const uint32_t bHiB = sm + OFF_BHI + bRel;
    const uint32_t bLoB = sm + OFF_BLO + bRel;

    float acc[2][8][4];
#pragma unroll
    for (int mt = 0; mt < 2; mt++)
#pragma unroll
        for (int nt = 0; nt < 8; nt++)
#pragma unroll
            for (int q = 0; q < 4; q++) acc[mt][nt][q] = 0.f;

    for (int kt = 0; kt < DDIM / 64; kt++) {
        __syncthreads();
        // A tiles: 128 rows x 64 halves (hi+lo), 1024 uint4 slots each
#pragma unroll
        for (int it = 0; it < 4; it++) {
            const int idx = tid + it * 256;
            const int r = idx >> 3, c8 = (idx & 7) << 3;
            const size_t g = (size_t)(m0 + r) * DDIM + kt * 64 + c8;
            const uint32_t so = (uint32_t)((r * XA_STRIDE + c8) * 2);
            *(uint4*)(xsmem + OFF_AHI + so) = *(const uint4*)(g_Ahi + g);
            *(uint4*)(xsmem + OFF_ALO + so) = *(const uint4*)(g_Alo + g);
        }
        // B tiles: 64 rows x 128 halves (hi+lo)
#pragma unroll
        for (int it = 0; it < 4; it++) {
            const int idx = tid + it * 256;
            const int r = idx >> 4, c8 = (idx & 15) << 3;
            const size_t g = (size_t)(kt * 64 + r) * FDIM + n0 + c8;
            const uint32_t so = (uint32_t)((r * XB_STRIDE + c8) * 2);
            *(uint4*)(xsmem + OFF_BHI + so) = *(const uint4*)(g_Whi + g);
            *(uint4*)(xsmem + OFF_BLO + so) = *(const uint4*)(g_Wlo + g);
        }
        __syncthreads();

#pragma unroll
        for (int kc = 0; kc < 4; kc++) {
            uint32_t ah[2][4], al[2][4];
            ldsm4_(ah[0], aHiB[0] + kc * 32);
            ldsm4_(ah[1], aHiB[1] + kc * 32);
            ldsm4_(al[0], aLoB[0] + kc * 32);
            ldsm4_(al[1], aLoB[1] + kc * 32);
            const uint32_t kOff = (uint32_t)(kc * 16 * XB_STRIDE * 2);
#pragma unroll
            for (int nt16 = 0; nt16 < 4; nt16++) {
                uint32_t bh[4], bl[4];
                ldsm4t_(bh, bHiB + kOff + nt16 * 32);
                ldsm4t_(bl, bLoB + kOff + nt16 * 32);
#pragma unroll
                for (int mt = 0; mt < 2; mt++) {
                    float* d0 = acc[mt][2 * nt16];
                    float* d1 = acc[mt][2 * nt16 + 1];
                    mma16816_(d0, ah[mt], bh[0], bh[1]);
                    mma16816_(d0, ah[mt], bl[0], bl[1]);
                    mma16816_(d0, al[mt], bh[0], bh[1]);
                    mma16816_(d1, ah[mt], bh[2], bh[3]);
                    mma16816_(d1, ah[mt], bl[2], bl[3]);
                    mma16816_(d1, al[mt], bh[2], bh[3]);
                }
            }
        }
    }

    // epilogue: c0,c1 -> row g, cols tg*2,+1 ; c2,c3 -> row g+8
    const int g  = lane >> 2;
    const int tg = lane & 3;
#pragma unroll
    for (int mt = 0; mt < 2; mt++) {
#pragma unroll
        for (int nt = 0; nt < 8; nt++) {
            const int row = m0 + m_w + mt * 16 + g;
            const int col = n0 + n_w + nt * 8 + tg * 2;
            const float2 b2 = *(const float2*)&bias[col];
            *(float2*)&C[(size_t)row * FDIM + col] =
                make_float2(acc[mt][nt][0] + b2.x, acc[mt][nt][1] + b2.y);
            *(float2*)&C[(size_t)(row + 8) * FDIM + col] =
                make_float2(acc[mt][nt][2] + b2.x, acc[mt][nt][3] + b2.y);
        }
    }
}

// ----------------------------------------------------------------------------
// Phase 2: sequential scan (round-8 version, unchanged — known good)
// ----------------------------------------------------------------------------
#define SMB_RED   16384
#define SMB_MBAR  49152
#define SMB_TOTAL 49184
#define H_STRIDE  (NB * 512)
#define H_BYTES   (NB * 512 * 4)
#define TX_BYTES  (CLUSTER * 256 * 4)

__device__ __forceinline__ void cluster_sync_() {
    asm volatile("barrier.cluster.arrive.aligned;" ::: "memory");
    asm volatile("barrier.cluster.wait.aligned;" ::: "memory");
}
__device__ __forceinline__ void mbar_init_(uint32_t mbar, uint32_t cnt) {
    asm volatile("mbarrier.init.shared.b64 [%0], %1;" :: "r"(mbar), "r"(cnt)
                 : "memory");
}
__device__ __forceinline__ void mbar_expect_tx_(uint32_t mbar, uint32_t bytes) {
    asm volatile("mbarrier.arrive.expect_tx.shared.b64 _, [%0], %1;"
                 :: "r"(mbar), "r"(bytes) : "memory");
}
__device__ __forceinline__ void wait_parity_(uint32_t mbar, uint32_t phase) {
    asm volatile(
        "{\n\t"
        ".reg .pred P;\n\t"
        "WL%=:\n\t"
        "mbarrier.try_wait.parity.acquire.cluster.shared::cta.b64 P, [%0], %1, 0x989680;\n\t"
        "@P bra.uni WD%=;\n\t"
        "bra.uni WL%=;\n\t"
        "WD%=:\n\t"
        "}"
        :: "r"(mbar), "r"(phase) : "memory");
}
__device__ __forceinline__ void st_async_f32_(uint32_t raddr, float v,
                                              uint32_t rmbar) {
    asm volatile(
        "st.async.shared::cluster.mbarrier::complete_tx::bytes.b32 [%0], %1, [%2];"
        :: "r"(raddr), "r"(__float_as_uint(v)), "r"(rmbar) : "memory");
}
__device__ __forceinline__ float f4get(const float4 v, int j) {
    return j == 0 ? v.x : (j == 1 ? v.y : (j == 2 ? v.z : v.w));
}

extern __shared__ float smem2[];

__global__ __launch_bounds__(256, 1) __cluster_dims__(CLUSTER, 1, 1)
void rnn_scan_kernel(const float* __restrict__ w_hh,
                     float* __restrict__ xo)
{
    float* H   = smem2;
    float* RED = smem2 + SMB_RED / 4;

    const int tid  = threadIdx.x;
    const int rank = blockIdx.x % CLUSTER;
    const int bg   = blockIdx.x / CLUSTER;
    const int f0   = rank * FCHUNK;

    const int f4    = tid & 15;
    const int ks    = tid >> 4;
    const int kbase = ks * 32;
    const int ob = tid >> 6;
    const int of = tid & 63;
    float* xo_ptr = xo + (size_t)(bg * NB + ob) * TSTEPS * FDIM + f0 + of;

    float4 w4[32];
    {
        const float* wp = w_hh + (size_t)kbase * FDIM + f0 + (f4 << 2);
#pragma unroll
        for (int kk = 0; kk < 32; kk++)
            w4[kk] = *(const float4*)(wp + (size_t)kk * FDIM);
    }

    uint32_t sbase;
    asm("{ .reg .u64 t; cvta.to.shared.u64 t, %1; cvt.u32.u64 %0, t; }"
        : "=r"(sbase) : "l"(smem2));
    const uint32_t mbar0 = sbase + SMB_MBAR;

    if (tid == 0) {
        mbar_init_(mbar0, 1);
        mbar_init_(mbar0 + 8, 1);
    }
    for (int i = tid; i < H_STRIDE; i += 256) H[H_STRIDE + i] = 0.f;
    __syncthreads();
    if (tid == 0) mbar_expect_tx_(mbar0, TX_BYTES);
    cluster_sync_();

    const uint32_t h0_byte = (uint32_t)((ob * 512 + f0 + of) * 4);
    uint32_t ra0[CLUSTER];
#pragma unroll
    for (int r = 0; r < CLUSTER; r++) {
        asm("mapa.shared::cluster.u32 %0, %1, %2;"
            : "=r"(ra0[r]) : "r"(sbase + h0_byte), "r"(r));
    }
    const uint32_t d_mb = (uint32_t)SMB_MBAR - h0_byte;

#pragma unroll 1
    for (int t = 0; t < TSTEPS; t++) {
        const int p = t & 1;
        const float xpv = xo_ptr[t * FDIM];

        if (t > 0)
            wait_parity_(mbar0 + (1 - p) * 8, ((uint32_t)(t - 1) >> 1) & 1);
        if (tid == 0 && t < TSTEPS - 2)
            mbar_expect_tx_(mbar0 + (1 - p) * 8, TX_BYTES);

        const float* hp = H + (1 - p) * H_STRIDE;

        float acc[NB][4];
#pragma unroll
        for (int b = 0; b < NB; b++)
#pragma unroll
            for (int j = 0; j < 4; j++) acc[b][j] = 0.f;

#pragma unroll
        for (int kk = 0; kk < 32; kk += 4) {
            const int k = kbase + kk;
            float4 hq[NB];
#pragma unroll
            for (int b = 0; b < NB; b++)
                hq[b] = *(const float4*)&hp[b * 512 + k];
#pragma unroll
            for (int j = 0; j < 4; j++) {
                const float4 w = w4[kk + j];
#pragma unroll
                for (int b = 0; b < NB; b++) {
                    const float hb = f4get(hq[b], j);
                    acc[b][0] = fmaf(hb, w.x, acc[b][0]);
                    acc[b][1] = fmaf(hb, w.y, acc[b][1]);
                    acc[b][2] = fmaf(hb, w.z, acc[b][2]);
                    acc[b][3] = fmaf(hb, w.w, acc[b][3]);
                }
            }
        }

        float* REDp = RED + p * (16 * 256);
#pragma unroll
        for (int b = 0; b < NB; b++) {
            *(float4*)&REDp[ks * 256 + b * 64 + (f4 << 2)] =
                make_float4(acc[b][0], acc[b][1], acc[b][2], acc[b][3]);
        }
        __syncthreads();

        float z0 = 0.f, z1 = 0.f, z2 = 0.f, z3 = 0.f;
#pragma unroll
        for (int s = 0; s < 16; s += 4) {
            z0 += REDp[(s + 0) * 256 + tid];
            z1 += REDp[(s + 1) * 256 + tid];
            z2 += REDp[(s + 2) * 256 + tid];
            z3 += REDp[(s + 3) * 256 + tid];
        }
        const float hv = tanhf(xpv + ((z0 + z1) + (z2 + z3)));

        xo_ptr[t * FDIM] = hv;

        if (t < TSTEPS - 1) {
            const uint32_t rb = (uint32_t)(p * H_BYTES);
            const uint32_t db = d_mb + (uint32_t)(p * 8);
#pragma unroll
            for (int r = 0; r < CLUSTER; r++)
                st_async_f32_(ra0[r] + rb, hv, ra0[r] + db);
        }
    }
}

// ----------------------------------------------------------------------------
extern "C" void kernel_launch(void* const* d_in, const int* in_sizes, int n_in,
                              void* d_out, int out_size)
{
    const float* inputs = (const float*)d_in[0];  // [64,1024,512]
    const float* w_ih   = (const float*)d_in[1];  // [512,512]
    const float* w_hh   = (const float*)d_in[2];  // [512,512]
    const float* bias   = (const float*)d_in[3];  // [512]
    float* out = (float*)d_out;                   // [64,1024,512]

    cudaFuncSetAttribute(xproj_mma_kernel,
                         cudaFuncAttributeMaxDynamicSharedMemorySize, XP_SMEM);
    cudaFuncSetAttribute(rnn_scan_kernel,
                         cudaFuncAttributeMaxDynamicSharedMemorySize, SMB_TOTAL);

    // Phase 0: split fp32 -> bf16 hi/lo scratch
    conv_A_kernel<<<((size_t)MTOT * DDIM) / (256 * 4), 256>>>(inputs);
    conv_W_kernel<<<(DDIM * FDIM) / (256 * 4), 256>>>(w_ih);

    // Phase 1: x_proj via split-bf16 tensor-core GEMM
    {
        dim3 grid(FDIM / 128, MTOT / 128);  // (4, 512)
        xproj_mma_kernel<<<grid, 256, XP_SMEM>>>(bias, out);
    }
    // Phase 2: sequential scan (clustered persistent kernel)
    {
        rnn_scan_kernel<<<NCTA2, 256, SMB_TOTAL>>>(w_hh, out);
    }
}

// round 11
// speedup vs baseline: 1.6091x; 1.6091x over previous
#include <cuda_runtime.h>
#include <cuda_bf16.h>
#include <cstdint>

#define BATCH  64
#define TSTEPS 1024
#define DDIM   512
#define FDIM   512
#define MTOT   (BATCH * TSTEPS)   // 65536

#define CLUSTER 8
#define NB      4
#define FCHUNK  64
#define NCLUST  (BATCH / NB)
#define NCTA2   (NCLUST * CLUSTER)

// ---------------------------------------------------------------------------
// Split-bf16 scratch (device globals: allowed scratch, no allocation)
// ---------------------------------------------------------------------------
__device__ __nv_bfloat16 g_Ahi[(size_t)MTOT * DDIM];   // 64 MB
__device__ __nv_bfloat16 g_Alo[(size_t)MTOT * DDIM];   // 64 MB
__device__ __nv_bfloat16 g_Whi[DDIM * FDIM];           // 512 KB
__device__ __nv_bfloat16 g_Wlo[DDIM * FDIM];           // 512 KB

__device__ __forceinline__ void split2_(float v, unsigned short& h, unsigned short& l) {
    __nv_bfloat16 hb = __float2bfloat16_rn(v);
    __nv_bfloat16 lb = __float2bfloat16_rn(v - __bfloat162float(hb));
    h = __bfloat16_as_ushort(hb);
    l = __bfloat16_as_ushort(lb);
}

__global__ __launch_bounds__(256) void conv_A_kernel(const float* __restrict__ in) {
    size_t i = ((size_t)blockIdx.x * blockDim.x + threadIdx.x) * 4;
    float4 v = *(const float4*)(in + i);
    unsigned short h0, h1, h2, h3, l0, l1, l2, l3;
    split2_(v.x, h0, l0); split2_(v.y, h1, l1);
    split2_(v.z, h2, l2); split2_(v.w, h3, l3);
    uint2 ph = make_uint2((uint32_t)h0 | ((uint32_t)h1 << 16),
                          (uint32_t)h2 | ((uint32_t)h3 << 16));
    uint2 pl = make_uint2((uint32_t)l0 | ((uint32_t)l1 << 16),
                          (uint32_t)l2 | ((uint32_t)l3 << 16));
    *(uint2*)(g_Ahi + i) = ph;
    *(uint2*)(g_Alo + i) = pl;
}

__global__ __launch_bounds__(256) void conv_W_kernel(const float* __restrict__ in) {
    size_t i = ((size_t)blockIdx.x * blockDim.x + threadIdx.x) * 4;
    float4 v = *(const float4*)(in + i);
    unsigned short h0, h1, h2, h3, l0, l1, l2, l3;
    split2_(v.x, h0, l0); split2_(v.y, h1, l1);
    split2_(v.z, h2, l2); split2_(v.w, h3, l3);
    uint2 ph = make_uint2((uint32_t)h0 | ((uint32_t)h1 << 16),
                          (uint32_t)h2 | ((uint32_t)h3 << 16));
    uint2 pl = make_uint2((uint32_t)l0 | ((uint32_t)l1 << 16),
                          (uint32_t)l2 | ((uint32_t)l3 << 16));
    *(uint2*)(g_Whi + i) = ph;
    *(uint2*)(g_Wlo + i) = pl;
}

// ---------------------------------------------------------------------------
// Phase 1: x_proj = A @ W + bias via split-bf16 HMMA (3 products, fp32 acc)
// CTA tile 128x128, K-tile 64; 8 warps as 4(M) x 2(N), warp tile 32x64.
// FIX vs round 9: launch_bounds(256,1) (no spills) + cp.async double buffer.
// ---------------------------------------------------------------------------
#define XA_STRIDE 72
#define XB_STRIDE 136
#define OFF_AHI 0
#define OFF_ALO 18432
#define OFF_BHI 36864
#define OFF_BLO 54272
#define XP_STAGE 71680
#define XP_SMEM  (2 * XP_STAGE)   // 143360

__device__ __forceinline__ void ldsm4_(uint32_t* r, uint32_t addr) {
    asm volatile("ldmatrix.sync.aligned.m8n8.x4.shared.b16 {%0,%1,%2,%3}, [%4];"
                 : "=r"(r[0]), "=r"(r[1]), "=r"(r[2]), "=r"(r[3]) : "r"(addr));
}
__device__ __forceinline__ void ldsm4t_(uint32_t* r, uint32_t addr) {
    asm volatile("ldmatrix.sync.aligned.m8n8.x4.trans.shared.b16 {%0,%1,%2,%3}, [%4];"
                 : "=r"(r[0]), "=r"(r[1]), "=r"(r[2]), "=r"(r[3]) : "r"(addr));
}
__device__ __forceinline__ void mma16816_(float* d, const uint32_t* a,
                                          uint32_t b0, uint32_t b1) {
    asm volatile(
        "mma.sync.aligned.m16n8k16.row.col.f32.bf16.bf16.f32 "
        "{%0,%1,%2,%3}, {%4,%5,%6,%7}, {%8,%9}, {%0,%1,%2,%3};"
        : "+f"(d[0]), "+f"(d[1]), "+f"(d[2]), "+f"(d[3])
        : "r"(a[0]), "r"(a[1]), "r"(a[2]), "r"(a[3]), "r"(b0), "r"(b1));
}
__device__ __forceinline__ void cpasync16_(uint32_t s, const void* g) {
    asm volatile("cp.async.cg.shared.global [%0], [%1], 16;"
                 :: "r"(s), "l"(g) : "memory");
}

extern __shared__ char xsmem[];

__global__ __launch_bounds__(256, 1) void xproj_mma_kernel(
    const float* __restrict__ bias,  // [512]
    float* __restrict__ C)           // [65536, 512]
{
    const int tid  = threadIdx.x;
    const int lane = tid & 31;
    const int wid  = tid >> 5;
    const int m0 = blockIdx.y * 128;
    const int n0 = blockIdx.x * 128;
    const int m_w = (wid >> 1) * 32;   // warp M offset in tile
    const int n_w = (wid & 1) * 64;    // warp N offset in tile

    uint32_t sm;
    asm("{ .reg .u64 t; cvta.to.shared.u64 t, %1; cvt.u32.u64 %0, t; }"
        : "=r"(sm) : "l"(xsmem));

    // per-thread cp.async source/dest precomputation
    const int a_r  = tid >> 1;              // 0..127 (A: 2 slots/row per it-step? no:)
    // A: 1024 16B-slots per hi/lo plane: idx = tid + it*256; r=idx>>3, c8=(idx&7)<<3
    // B: 1024 slots: r=idx>>4, c8=(idx&15)<<3
    (void)a_r;

    // ldmatrix lane addressing (canonical m16n8k16 mapping)
    const int a_row   = (lane & 15);
    const int a_khalf = (lane >> 4) & 1;
    const int b_krow  = (lane & 7) + (((lane >> 3) & 1) << 3);
    const int b_ncol8 = ((lane >> 4) & 1) << 3;

    // stage-relative fragment byte offsets
    uint32_t aHiR[2], aLoR[2];
#pragma unroll
    for (int mt = 0; mt < 2; mt++) {
        const uint32_t rb =
            (uint32_t)(((m_w + mt * 16 + a_row) * XA_STRIDE + a_khalf * 8) * 2);
        aHiR[mt] = OFF_AHI + rb;
        aLoR[mt] = OFF_ALO + rb;
    }
    const uint32_t bRel = (uint32_t)((b_krow * XB_STRIDE + n_w + b_ncol8) * 2);
    const uint32_t bHiR = OFF_BHI + bRel;
    const uint32_t bLoR = OFF_BLO + bRel;

    float acc[2][8][4];
#pragma unroll
    for (int mt = 0; mt < 2; mt++)
#pragma unroll
        for (int nt = 0; nt < 8; nt++)
#pragma unroll
            for (int q = 0; q < 4; q++) acc[mt][nt][q] = 0.f;

    // tile loader: issue cp.asyncs for K-tile kt into stage s
    auto load_tile = [&](int kt, int s) {
        const uint32_t stage = sm + (uint32_t)(s * XP_STAGE);
#pragma unroll
        for (int it = 0; it < 4; it++) {
            const int idx = tid + it * 256;
            const int r = idx >> 3, c8 = (idx & 7) << 3;
            const size_t g = (size_t)(m0 + r) * DDIM + kt * 64 + c8;
            const uint32_t so = (uint32_t)((r * XA_STRIDE + c8) * 2);
            cpasync16_(stage + OFF_AHI + so, g_Ahi + g);
            cpasync16_(stage + OFF_ALO + so, g_Alo + g);
        }
#pragma unroll
        for (int it = 0; it < 4; it++) {
            const int idx = tid + it * 256;
            const int r = idx >> 4, c8 = (idx & 15) << 3;
            const size_t g = (size_t)(kt * 64 + r) * FDIM + n0 + c8;
            const uint32_t so = (uint32_t)((r * XB_STRIDE + c8) * 2);
            cpasync16_(stage + OFF_BHI + so, g_Whi + g);
            cpasync16_(stage + OFF_BLO + so, g_Wlo + g);
        }
        asm volatile("cp.async.commit_group;" ::: "memory");
    };

    load_tile(0, 0);

#pragma unroll 1
    for (int kt = 0; kt < DDIM / 64; kt++) {
        if (kt < DDIM / 64 - 1) {
            load_tile(kt + 1, (kt + 1) & 1);
            asm volatile("cp.async.wait_group 1;" ::: "memory");
        } else {
            asm volatile("cp.async.wait_group 0;" ::: "memory");
        }
        __syncthreads();

        const uint32_t stage = sm + (uint32_t)((kt & 1) * XP_STAGE);
#pragma unroll
        for (int kc = 0; kc < 4; kc++) {
            uint32_t ah[2][4], al[2][4];
            ldsm4_(ah[0], stage + aHiR[0] + kc * 32);
            ldsm4_(ah[1], stage + aHiR[1] + kc * 32);
            ldsm4_(al[0], stage + aLoR[0] + kc * 32);
            ldsm4_(al[1], stage + aLoR[1] + kc * 32);
            const uint32_t kOff = (uint32_t)(kc * 16 * XB_STRIDE * 2);
#pragma unroll
            for (int nt16 = 0; nt16 < 4; nt16++) {
                uint32_t bh[4], bl[4];
                ldsm4t_(bh, stage + bHiR + kOff + nt16 * 32);
                ldsm4t_(bl, stage + bLoR + kOff + nt16 * 32);
#pragma unroll
                for (int mt = 0; mt < 2; mt++) {
                    float* d0 = acc[mt][2 * nt16];
                    float* d1 = acc[mt][2 * nt16 + 1];
                    mma16816_(d0, ah[mt], bh[0], bh[1]);
                    mma16816_(d0, ah[mt], bl[0], bl[1]);
                    mma16816_(d0, al[mt], bh[0], bh[1]);
                    mma16816_(d1, ah[mt], bh[2], bh[3]);
                    mma16816_(d1, ah[mt], bl[2], bl[3]);
                    mma16816_(d1, al[mt], bh[2], bh[3]);
                }
            }
        }
        __syncthreads();
    }

    // epilogue: c0,c1 -> row g, cols tg*2,+1 ; c2,c3 -> row g+8
    const int g  = lane >> 2;
    const int tg = lane & 3;
#pragma unroll
    for (int mt = 0; mt < 2; mt++) {
#pragma unroll
        for (int nt = 0; nt < 8; nt++) {
            const int row = m0 + m_w + mt * 16 + g;
            const int col = n0 + n_w + nt * 8 + tg * 2;
            const float2 b2 = *(const float2*)&bias[col];
            *(float2*)&C[(size_t)row * FDIM + col] =
                make_float2(acc[mt][nt][0] + b2.x, acc[mt][nt][1] + b2.y);
            *(float2*)&C[(size_t)(row + 8) * FDIM + col] =
                make_float2(acc[mt][nt][2] + b2.x, acc[mt][nt][3] + b2.y);
        }
    }
}

// ----------------------------------------------------------------------------
// Phase 2: sequential scan (round-8 version, unchanged — known good)
// ----------------------------------------------------------------------------
#define SMB_RED   16384
#define SMB_MBAR  49152
#define SMB_TOTAL 49184
#define H_STRIDE  (NB * 512)
#define H_BYTES   (NB * 512 * 4)
#define TX_BYTES  (CLUSTER * 256 * 4)

__device__ __forceinline__ void cluster_sync_() {
    asm volatile("barrier.cluster.arrive.aligned;" ::: "memory");
    asm volatile("barrier.cluster.wait.aligned;" ::: "memory");
}
__device__ __forceinline__ void mbar_init_(uint32_t mbar, uint32_t cnt) {
    asm volatile("mbarrier.init.shared.b64 [%0], %1;" :: "r"(mbar), "r"(cnt)
                 : "memory");
}
__device__ __forceinline__ void mbar_expect_tx_(uint32_t mbar, uint32_t bytes) {
    asm volatile("mbarrier.arrive.expect_tx.shared.b64 _, [%0], %1;"
                 :: "r"(mbar), "r"(bytes) : "memory");
}
__device__ __forceinline__ void wait_parity_(uint32_t mbar, uint32_t phase) {
    asm volatile(
        "{\n\t"
        ".reg .pred P;\n\t"
        "WL%=:\n\t"
        "mbarrier.try_wait.parity.acquire.cluster.shared::cta.b64 P, [%0], %1, 0x989680;\n\t"
        "@P bra.uni WD%=;\n\t"
        "bra.uni WL%=;\n\t"
        "WD%=:\n\t"
        "}"
        :: "r"(mbar), "r"(phase) : "memory");
}
__device__ __forceinline__ void st_async_f32_(uint32_t raddr, float v,
                                              uint32_t rmbar) {
    asm volatile(
        "st.async.shared::cluster.mbarrier::complete_tx::bytes.b32 [%0], %1, [%2];"
        :: "r"(raddr), "r"(__float_as_uint(v)), "r"(rmbar) : "memory");
}
__device__ __forceinline__ float f4get(const float4 v, int j) {
    return j == 0 ? v.x : (j == 1 ? v.y : (j == 2 ? v.z : v.w));
}

extern __shared__ float smem2[];

__global__ __launch_bounds__(256, 1) __cluster_dims__(CLUSTER, 1, 1)
void rnn_scan_kernel(const float* __restrict__ w_hh,
                     float* __restrict__ xo)
{
    float* H   = smem2;
    float* RED = smem2 + SMB_RED / 4;

    const int tid  = threadIdx.x;
    const int rank = blockIdx.x % CLUSTER;
    const int bg   = blockIdx.x / CLUSTER;
    const int f0   = rank * FCHUNK;

    const int f4    = tid & 15;
    const int ks    = tid >> 4;
    const int kbase = ks * 32;
    const int ob = tid >> 6;
    const int of = tid & 63;
    float* xo_ptr = xo + (size_t)(bg * NB + ob) * TSTEPS * FDIM + f0 + of;

    float4 w4[32];
    {
        const float* wp = w_hh + (size_t)kbase * FDIM + f0 + (f4 << 2);
#pragma unroll
        for (int kk = 0; kk < 32; kk++)
            w4[kk] = *(const float4*)(wp + (size_t)kk * FDIM);
    }

    uint32_t sbase;
    asm("{ .reg .u64 t; cvta.to.shared.u64 t, %1; cvt.u32.u64 %0, t; }"
        : "=r"(sbase) : "l"(smem2));
    const uint32_t mbar0 = sbase + SMB_MBAR;

    if (tid == 0) {
        mbar_init_(mbar0, 1);
        mbar_init_(mbar0 + 8, 1);
    }
    for (int i = tid; i < H_STRIDE; i += 256) H[H_STRIDE + i] = 0.f;
    __syncthreads();
    if (tid == 0) mbar_expect_tx_(mbar0, TX_BYTES);
    cluster_sync_();

    const uint32_t h0_byte = (uint32_t)((ob * 512 + f0 + of) * 4);
    uint32_t ra0[CLUSTER];
#pragma unroll
    for (int r = 0; r < CLUSTER; r++) {
        asm("mapa.shared::cluster.u32 %0, %1, %2;"
            : "=r"(ra0[r]) : "r"(sbase + h0_byte), "r"(r));
    }
    const uint32_t d_mb = (uint32_t)SMB_MBAR - h0_byte;

#pragma unroll 1
    for (int t = 0; t < TSTEPS; t++) {
        const int p = t & 1;
        const float xpv = xo_ptr[t * FDIM];

        if (t > 0)
            wait_parity_(mbar0 + (1 - p) * 8, ((uint32_t)(t - 1) >> 1) & 1);
        if (tid == 0 && t < TSTEPS - 2)
            mbar_expect_tx_(mbar0 + (1 - p) * 8, TX_BYTES);

        const float* hp = H + (1 - p) * H_STRIDE;

        float acc[NB][4];
#pragma unroll
        for (int b = 0; b < NB; b++)
#pragma unroll
            for (int j = 0; j < 4; j++) acc[b][j] = 0.f;

#pragma unroll
        for (int kk = 0; kk < 32; kk += 4) {
            const int k = kbase + kk;
            float4 hq[NB];
#pragma unroll
            for (int b = 0; b < NB; b++)
                hq[b] = *(const float4*)&hp[b * 512 + k];
#pragma unroll
            for (int j = 0; j < 4; j++) {
                const float4 w = w4[kk + j];
#pragma unroll
                for (int b = 0; b < NB; b++) {
                    const float hb = f4get(hq[b], j);
                    acc[b][0] = fmaf(hb, w.x, acc[b][0]);
                    acc[b][1] = fmaf(hb, w.y, acc[b][1]);
                    acc[b][2] = fmaf(hb, w.z, acc[b][2]);
                    acc[b][3] = fmaf(hb, w.w, acc[b][3]);
                }
            }
        }

        float* REDp = RED + p * (16 * 256);
#pragma unroll
        for (int b = 0; b < NB; b++) {
            *(float4*)&REDp[ks * 256 + b * 64 + (f4 << 2)] =
                make_float4(acc[b][0], acc[b][1], acc[b][2], acc[b][3]);
        }
        __syncthreads();

        float z0 = 0.f, z1 = 0.f, z2 = 0.f, z3 = 0.f;
#pragma unroll
        for (int s = 0; s < 16; s += 4) {
            z0 += REDp[(s + 0) * 256 + tid];
            z1 += REDp[(s + 1) * 256 + tid];
            z2 += REDp[(s + 2) * 256 + tid];
            z3 += REDp[(s + 3) * 256 + tid];
        }
        const float hv = tanhf(xpv + ((z0 + z1) + (z2 + z3)));

        xo_ptr[t * FDIM] = hv;

        if (t < TSTEPS - 1) {
            const uint32_t rb = (uint32_t)(p * H_BYTES);
            const uint32_t db = d_mb + (uint32_t)(p * 8);
#pragma unroll
            for (int r = 0; r < CLUSTER; r++)
                st_async_f32_(ra0[r] + rb, hv, ra0[r] + db);
        }
    }
}

// ----------------------------------------------------------------------------
extern "C" void kernel_launch(void* const* d_in, const int* in_sizes, int n_in,
                              void* d_out, int out_size)
{
    const float* inputs = (const float*)d_in[0];  // [64,1024,512]
    const float* w_ih   = (const float*)d_in[1];  // [512,512]
    const float* w_hh   = (const float*)d_in[2];  // [512,512]
    const float* bias   = (const float*)d_in[3];  // [512]
    float* out = (float*)d_out;                   // [64,1024,512]

    cudaFuncSetAttribute(xproj_mma_kernel,
                         cudaFuncAttributeMaxDynamicSharedMemorySize, XP_SMEM);
    cudaFuncSetAttribute(rnn_scan_kernel,
                         cudaFuncAttributeMaxDynamicSharedMemorySize, SMB_TOTAL);

    // Phase 0: split fp32 -> bf16 hi/lo scratch
    conv_A_kernel<<<((size_t)MTOT * DDIM) / (256 * 4), 256>>>(inputs);
    conv_W_kernel<<<(DDIM * FDIM) / (256 * 4), 256>>>(w_ih);

    // Phase 1: x_proj via split-bf16 tensor-core GEMM
    {
        dim3 grid(FDIM / 128, MTOT / 128);  // (4, 512)
        xproj_mma_kernel<<<grid, 256, XP_SMEM>>>(bias, out);
    }
    // Phase 2: sequential scan (clustered persistent kernel)
    {
        rnn_scan_kernel<<<NCTA2, 256, SMB_TOTAL>>>(w_hh, out);
    }
}